// round 15
// baseline (speedup 1.0000x reference)
#include <cuda_runtime.h>
#include <cuda_bf16.h>
#include <math.h>
#include <stdint.h>

#define NB    16
#define CIN_  384
#define CG    768
#define FEAT_ 192
#define HH    64
#define WW    64
#define HSZ   (NB * FEAT_ * WW)

// Scratch (device globals; no allocations allowed)
__device__ __nv_bfloat16 g_hb[NB * CG * HH * WW];   // shuffled gate inputs, bf16
__device__ __nv_bfloat16 g_Wb2[CG * 768];           // i2s weights [oc'][k=tap*384+ic], bf16, masked
__device__ __nv_bfloat16 g_xb[NB * 2 * CIN_ * HH * WW]; // x, tap-shifted bf16
__device__ __nv_bfloat16 g_w1rb[24 * 3 * 32 * 192]; // s2s weights [ftile][t][ocr][kf], bf16
__device__ __nv_bfloat16 g_wsktb[CIN_ * FEAT_];     // skip weights [co][ci], bf16
__device__ __nv_bfloat16 g_hsh[2][3][HSZ];          // hidden, tap-shifted bf16, double buffered
__device__ __nv_bfloat16 g_outhb[NB * FEAT_ * HH * WW]; // scan outputs, bf16
__device__ unsigned g_rowbar[NB * 32];              // per-bquad row barriers

__device__ __forceinline__ float sigf(float v) { return 1.0f / (1.0f + __expf(-v)); }
__device__ __forceinline__ float tanhfast(float x) {
    float y; asm("tanh.approx.f32 %0, %1;" : "=f"(y) : "f"(x)); return y;
}
__device__ __forceinline__ uint32_t smem_u32(const void* p) {
    uint32_t a;
    asm("{ .reg .u64 t; cvta.to.shared.u64 t, %1; cvt.u32.u64 %0, t; }" : "=r"(a) : "l"(p));
    return a;
}
__device__ __forceinline__ uint32_t pk2(float lo, float hi) {
    uint32_t r; asm("cvt.rn.bf16x2.f32 %0, %1, %2;" : "=r"(r) : "f"(hi), "f"(lo));
    return r;
}
__device__ __forceinline__ float2 upk(uint32_t u) {
    __nv_bfloat162 t = *reinterpret_cast<__nv_bfloat162*>(&u);
    return __bfloat1622float2(t);
}
#define F2U(x) __float_as_uint(x)
#define CP_ASYNC16(dst, src) \
    asm volatile("cp.async.cg.shared.global [%0], [%1], 16;" :: "r"(dst), "l"(src) : "memory")
#define CP_COMMIT() asm volatile("cp.async.commit_group;" ::: "memory")
#define CP_WAIT1()  asm volatile("cp.async.wait_group 1;" ::: "memory")
#define CP_WAIT0()  asm volatile("cp.async.wait_group 0;" ::: "memory")

// bf16 m16n8k16
__device__ __forceinline__ void mma16(float* d, uint32_t a0, uint32_t a1, uint32_t a2, uint32_t a3,
                                      uint32_t b0, uint32_t b1) {
    asm volatile("mma.sync.aligned.m16n8k16.row.col.f32.bf16.bf16.f32 "
                 "{%0,%1,%2,%3}, {%4,%5,%6,%7}, {%8,%9}, {%0,%1,%2,%3};"
                 : "+f"(d[0]), "+f"(d[1]), "+f"(d[2]), "+f"(d[3])
                 : "r"(a0), "r"(a1), "r"(a2), "r"(a3), "r"(b0), "r"(b1));
}
#define LDSM_X4(r0, r1, r2, r3, a) \
    asm volatile("ldmatrix.sync.aligned.m8n8.x4.shared.b16 {%0,%1,%2,%3}, [%4];" \
                 : "=r"(r0), "=r"(r1), "=r"(r2), "=r"(r3) : "r"(a))
#define LDSM_X4T(r0, r1, r2, r3, a) \
    asm volatile("ldmatrix.sync.aligned.m8n8.x4.trans.shared.b16 {%0,%1,%2,%3}, [%4];" \
                 : "=r"(r0), "=r"(r1), "=r"(r2), "=r"(r3) : "r"(a))

// ---------------------------------------------------------------------------
// Weight prep + x tap-shift + state init (merged; launch covers MAX index!)
// ---------------------------------------------------------------------------
__global__ void prep_kernel(const float* __restrict__ x,
                            const float* __restrict__ w_i2s,
                            const float* __restrict__ w_s2s,
                            const float* __restrict__ w_skip) {
    int idx = blockIdx.x * blockDim.x + threadIdx.x;
    if (idx < CG * 768) {
        int ocp = idx / 768, k = idx % 768;
        int tap = k / 384, ic = k % 384;
        int q = ocp / 192, p = (ocp % 192) / 64, fl = ocp % 64;
        int c = p * 256 + q * 64 + fl;
        float v = w_i2s[((long)c * CIN_ + ic) * 3 + tap];
        if (tap == 1 && !(p >= (ic / 128))) v = 0.f;
        g_Wb2[idx] = __float2bfloat16(v);
    }
    if (idx < 24 * 3 * 32 * 192) {
        int ftile = idx / 18432;
        int r2 = idx % 18432;
        int t = r2 / 6144;
        int r3 = r2 % 6144;
        int ocr = r3 / 192, kf = r3 % 192;
        int gate = ocr >> 3, j = ocr & 7;
        int oc = gate * FEAT_ + ftile * 8 + j;
        g_w1rb[idx] = __float2bfloat16(w_s2s[((long)oc * FEAT_ + kf) * 3 + t]);
    }
    if (idx < CIN_ * FEAT_) {
        g_wsktb[idx] = __float2bfloat16(w_skip[idx]);
    }
    if (idx < 3 * HSZ / 2) ((uint32_t*)&g_hsh[0][0][0])[idx] = 0u;
    if (idx < NB * 32) g_rowbar[idx] = 0u;

    if (idx < NB * CIN_ * HH * 4) {      // x -> two tap-shifted bf16 copies
        int q = idx & 3, row = idx >> 2;
        int b = row / (CIN_ * HH);
        int rr = row % (CIN_ * HH);
        int ic = rr / HH, y = rr % HH;
        const float* src = x + ((long)(b * CIN_ + ic) * HH + y) * WW + q * 16;
        float v[17];
        v[0] = (q == 0) ? 0.f : src[-1];
#pragma unroll
        for (int j = 0; j < 4; j++) {
            float4 t = *(const float4*)(src + j * 4);
            v[1 + j * 4] = t.x; v[2 + j * 4] = t.y; v[3 + j * 4] = t.z; v[4 + j * 4] = t.w;
        }
        __nv_bfloat16* d0 = g_xb + ((long)((b * 2 + 0) * CIN_ + ic) * HH + y) * WW + q * 16;
        __nv_bfloat16* d1 = g_xb + ((long)((b * 2 + 1) * CIN_ + ic) * HH + y) * WW + q * 16;
        *(uint4*)d0 = make_uint4(pk2(v[0], v[1]), pk2(v[2], v[3]), pk2(v[4], v[5]), pk2(v[6], v[7]));
        *((uint4*)d0 + 1) = make_uint4(pk2(v[8], v[9]), pk2(v[10], v[11]), pk2(v[12], v[13]), pk2(v[14], v[15]));
        *(uint4*)d1 = make_uint4(pk2(v[1], v[2]), pk2(v[3], v[4]), pk2(v[5], v[6]), pk2(v[7], v[8]));
        *((uint4*)d1 + 1) = make_uint4(pk2(v[9], v[10]), pk2(v[11], v[12]), pk2(v[13], v[14]), pk2(v[15], v[16]));
    }
}

// ---------------------------------------------------------------------------
// i2s via bf16 m16n8k16 + ldmatrix; warp tile 32m x 64n; bf16 output (R13).
// ---------------------------------------------------------------------------
#define I2S_SMEM (2 * (18432 + 16384))

__global__ void __launch_bounds__(256, 2) i2s_bf16_kernel() {
    extern __shared__ char smc[];
    uint32_t sm32 = smem_u32(smc);

    int tid = threadIdx.x, lane = tid & 31, wid = tid >> 5;
    int OC0 = blockIdx.x * 128;
    int b = blockIdx.y >> 5, y0 = (blockIdx.y & 31) * 2;
    int m0 = (wid & 3) * 32;
    int n0 = (wid >> 2) * 64;

    const __nv_bfloat16* xbb = g_xb + (long)b * 2 * CIN_ * HH * WW;

    float d[2][8][4];
#pragma unroll
    for (int mt = 0; mt < 2; mt++)
#pragma unroll
        for (int nt = 0; nt < 8; nt++)
#pragma unroll
            for (int i = 0; i < 4; i++) d[mt][nt][i] = 0.f;

    auto issue = [&](int c, int buf) {
        uint32_t ab = sm32 + buf * 34816;
        uint32_t bb = ab + 18432;
        int tap = c / 6, ic0 = (c % 6) * 64;
#pragma unroll
        for (int j = 0; j < 4; j++) {
            int i = tid + j * 256;
            int row = i >> 3, seg = i & 7;
            CP_ASYNC16(ab + row * 144 + seg * 16,
                       g_Wb2 + (long)(OC0 + row) * 768 + c * 64 + seg * 8);
        }
#pragma unroll
        for (int j = 0; j < 4; j++) {
            int i = tid + j * 256;
            int k = i >> 4, n8 = i & 15, yr = n8 >> 3, w8 = n8 & 7;
            uint32_t da = bb + k * 256 + yr * 128 + ((w8 * 16) ^ ((k & 7) << 4));
            const __nv_bfloat16* sa = xbb + ((long)(tap * CIN_ + ic0 + k) * HH + y0 + yr) * WW + w8 * 8;
            CP_ASYNC16(da, sa);
        }
    };

    int kfl = lane & 15;
    int swz = (lane & 7) << 4;
    int col8b = (lane & 16) ? 1 : 0;

    issue(0, 0); CP_COMMIT();

    for (int c = 0; c < 12; c++) {
        if (c < 11) { issue(c + 1, (c + 1) & 1); CP_COMMIT(); CP_WAIT1(); }
        else CP_WAIT0();
        __syncthreads();

        uint32_t ab = sm32 + (c & 1) * 34816;
        uint32_t bb = ab + 18432;
#pragma unroll
        for (int kk = 0; kk < 4; kk++) {
            uint32_t a[2][4];
#pragma unroll
            for (int mt = 0; mt < 2; mt++) {
                uint32_t aaddr = ab + 2 * ((m0 + mt * 16 + (lane & 15)) * 72
                                           + kk * 16 + ((lane >> 4) << 3));
                LDSM_X4(a[mt][0], a[mt][1], a[mt][2], a[mt][3], aaddr);
            }
            uint32_t rowbase = bb + (kk * 16 + kfl) * 256;
#pragma unroll
            for (int j = 0; j < 4; j++) {
                int seg = (n0 >> 3) + j * 2 + col8b;
                uint32_t baddr = rowbase + ((seg >> 3) * 128) + (uint32_t)(((seg & 7) * 16) ^ swz);
                uint32_t b0, b1, b2, b3;
                LDSM_X4T(b0, b1, b2, b3, baddr);
#pragma unroll
                for (int mt = 0; mt < 2; mt++) {
                    mma16(d[mt][j * 2],     a[mt][0], a[mt][1], a[mt][2], a[mt][3], b0, b1);
                    mma16(d[mt][j * 2 + 1], a[mt][0], a[mt][1], a[mt][2], a[mt][3], b2, b3);
                }
            }
        }
        __syncthreads();
    }

    int y = y0 + (n0 >> 6);
#pragma unroll
    for (int mt = 0; mt < 2; mt++) {
        int ocl = OC0 + m0 + mt * 16 + (lane >> 2);
#pragma unroll
        for (int nt = 0; nt < 8; nt++) {
            int w = nt * 8 + (lane & 3) * 2;
            __nv_bfloat16* p0 = &g_hb[(((long)b * CG + ocl) * HH + y) * WW + w];
            *(uint32_t*)p0 = pk2(d[mt][nt][0], d[mt][nt][1]);
            *(uint32_t*)(p0 + (long)8 * HH * WW) = pk2(d[mt][nt][2], d[mt][nt][3]);
        }
    }
}

// ---------------------------------------------------------------------------
// Persistent LSTM scan v3: grid (24, 4) = 96 CTAs x 512 thr, 1 CTA/SM on ALL
// SMs (no sharing imbalance), 16 warps, 4 batches per CTA, weights shared.
// ---------------------------------------------------------------------------
#define SCAN_SMEM (38400 + 3 * 49152)

__global__ void __launch_bounds__(512, 1) lstm_scan_mma() {
    extern __shared__ char smc[];
    uint32_t* wstb_u = (uint32_t*)smc;                       // 9600 uints
    char* hpt = smc + 38400;                                 // 3 x 49152 bytes
    float* sbuf = (float*)hpt;                               // overlay buf0 (needs 34.8KB)
    uint32_t wstb32 = smem_u32(wstb_u);
    uint32_t hpt32 = smem_u32(hpt);

    int tid = threadIdx.x, lane = tid & 31, wid = tid >> 5;
    int ftile = blockIdx.x, bquad = blockIdx.y;
    int F0 = ftile * 8;
    int wbb = wid & 3;
    int m0 = ((wid >> 2) & 1) * 16;
    int n0 = (wid >> 3) * 32;
    int pbb = tid >> 7, fl = (tid >> 4) & 7, w0 = (tid & 15) * 4;

    {
        const uint32_t* src = (const uint32_t*)&g_w1rb[(long)ftile * 18432];
#pragma unroll
        for (int j = tid; j < 9216; j += 512)
            wstb_u[(j / 96) * 100 + (j % 96)] = src[j];
    }

    float creg[4] = {0.f, 0.f, 0.f, 0.f};
    uint2 hv[4];
    {
        int b = bquad * 4 + pbb;
#pragma unroll
        for (int g = 0; g < 4; g++)
            hv[g] = *(const uint2*)&g_hb[(((long)(b * CG + g * FEAT_ + F0 + fl)) * HH + 0) * WW + w0];
    }
    __syncthreads();

    unsigned* bar = &g_rowbar[bquad * 32];

    int a_row = (m0 + (lane & 15)) * 200 + ((lane >> 4) << 3);
    int kfl  = (lane & 7) + (lane & 8);
    int swz  = (lane & 7) << 4;
    int col8 = (lane & 16) ? 8 : 0;

    for (int y = 0; y < HH; y++) {
        const __nv_bfloat16* hsrc = &g_hsh[y & 1][0][0];

        auto issue_chunk = [&](int ch, int buf) {
            int f0k = ch * 32;
            uint32_t dbase = hpt32 + buf * 49152;
#pragma unroll
            for (int j = 0; j < 6; j++) {
                int i = tid + j * 512;
                int t = i >> 10, r = i & 1023, bb = r >> 8, kf = (r >> 3) & 31, w4 = r & 7;
                uint32_t da = dbase + (((t * 4 + bb) * 32 + kf) << 7)
                            + ((w4 * 16) ^ ((kf & 7) << 4));
                const __nv_bfloat16* sa = hsrc + (long)t * HSZ
                            + ((bquad * 4 + bb) * FEAT_ + f0k + kf) * WW + w4 * 8;
                CP_ASYNC16(da, sa);
            }
        };

        float d[4][4];
#pragma unroll
        for (int nt = 0; nt < 4; nt++)
#pragma unroll
            for (int i = 0; i < 4; i++) d[nt][i] = 0.f;

        issue_chunk(0, 0); CP_COMMIT();
        issue_chunk(1, 1); CP_COMMIT();

#pragma unroll
        for (int ch = 0; ch < 6; ch++) {
            if (ch < 5) CP_WAIT1(); else CP_WAIT0();
            __syncthreads();
            if (ch < 4) { issue_chunk(ch + 2, (ch + 2) % 3); CP_COMMIT(); }

            uint32_t hb = hpt32 + (ch % 3) * 49152;
            int kbase = ch * 32;
#pragma unroll
            for (int t = 0; t < 3; t++) {
#pragma unroll
                for (int kk = 0; kk < 2; kk++) {
                    uint32_t a0, a1, a2, a3;
                    uint32_t aaddr = wstb32 + 2 * (t * 6400 + a_row + kbase + kk * 16);
                    LDSM_X4(a0, a1, a2, a3, aaddr);
                    uint32_t rowoff = (uint32_t)(((t * 4 + wbb) * 32 + kk * 16 + kfl) << 7);
#pragma unroll
                    for (int nt2 = 0; nt2 < 2; nt2++) {
                        uint32_t b0, b1, b2, b3;
                        uint32_t baddr = hb + rowoff
                                       + ((uint32_t)((n0 + nt2 * 16 + col8) * 2) ^ (uint32_t)swz);
                        LDSM_X4T(b0, b1, b2, b3, baddr);
                        mma16(d[nt2 * 2],     a0, a1, a2, a3, b0, b1);
                        mma16(d[nt2 * 2 + 1], a0, a1, a2, a3, b2, b3);
                    }
                }
            }
        }

#pragma unroll
        for (int nt = 0; nt < 4; nt++) {
            int r = m0 + (lane >> 2);
            int cc = n0 + nt * 8 + (lane & 3) * 2;
            *(float2*)&sbuf[wbb * 2176 + r * 68 + cc] = make_float2(d[nt][0], d[nt][1]);
            *(float2*)&sbuf[wbb * 2176 + (r + 8) * 68 + cc] = make_float2(d[nt][2], d[nt][3]);
        }
        __syncthreads();

        int b = bquad * 4 + pbb;
        float hn[4];
        {
            float* sb = sbuf + pbb * 2176;
            float4 ov = *(const float4*)&sb[fl * 68 + w0];
            float4 fv = *(const float4*)&sb[(8 + fl) * 68 + w0];
            float4 iv = *(const float4*)&sb[(16 + fl) * 68 + w0];
            float4 gv = *(const float4*)&sb[(24 + fl) * 68 + w0];
            float hva[4][4];
#pragma unroll
            for (int g = 0; g < 4; g++) {
                float2 p0 = upk(hv[g].x), p1 = upk(hv[g].y);
                hva[g][0] = p0.x; hva[g][1] = p0.y; hva[g][2] = p1.x; hva[g][3] = p1.y;
            }
            float so[4] = {sigf(ov.x + hva[0][0]), sigf(ov.y + hva[0][1]),
                           sigf(ov.z + hva[0][2]), sigf(ov.w + hva[0][3])};
            float sf[4] = {sigf(fv.x + hva[1][0]), sigf(fv.y + hva[1][1]),
                           sigf(fv.z + hva[1][2]), sigf(fv.w + hva[1][3])};
            float si[4] = {sigf(iv.x + hva[2][0]), sigf(iv.y + hva[2][1]),
                           sigf(iv.z + hva[2][2]), sigf(iv.w + hva[2][3])};
            float sg[4] = {sigf(gv.x + hva[3][0]), sigf(gv.y + hva[3][1]),
                           sigf(gv.z + hva[3][2]), sigf(gv.w + hva[3][3])};
#pragma unroll
            for (int i = 0; i < 4; i++) {
                creg[i] = sf[i] * creg[i] + si[i] * sg[i];
                hn[i] = so[i] * tanhfast(creg[i]);
            }
            float lft = __shfl_up_sync(0xffffffffu, hn[3], 1);
            float rgt = __shfl_down_sync(0xffffffffu, hn[0], 1);
            if ((tid & 15) == 0) lft = 0.f;
            if ((tid & 15) == 15) rgt = 0.f;

            long fbase = ((long)(b * FEAT_ + F0 + fl)) * WW + w0;
            __nv_bfloat16* hbd = &g_hsh[(y & 1) ^ 1][0][0];
            *(uint2*)(hbd + fbase)           = make_uint2(pk2(lft, hn[0]), pk2(hn[1], hn[2]));
            *(uint2*)(hbd + HSZ + fbase)     = make_uint2(pk2(hn[0], hn[1]), pk2(hn[2], hn[3]));
            *(uint2*)(hbd + 2 * HSZ + fbase) = make_uint2(pk2(hn[1], hn[2]), pk2(hn[3], rgt));
        }
        __syncthreads();                 // all h-state stores done; sbuf consumed

        if (tid == 0 && y < HH - 1) {
            asm volatile("red.release.gpu.global.add.u32 [%0], %1;" :: "l"(bar), "r"(1u) : "memory");
        }
        {
            __nv_bfloat16* op = &g_outhb[((b * FEAT_ + F0 + fl) * HH + y) * WW + w0];
            *(uint2*)op = make_uint2(pk2(hn[0], hn[1]), pk2(hn[2], hn[3]));
        }
        if (y < HH - 1) {
#pragma unroll
            for (int g = 0; g < 4; g++)
                hv[g] = *(const uint2*)&g_hb[(((long)(b * CG + g * FEAT_ + F0 + fl)) * HH + (y + 1)) * WW + w0];
            if (tid == 0) {
                unsigned target = 24u * (unsigned)(y + 1);
                unsigned v;
                do {
                    asm volatile("ld.acquire.gpu.global.u32 %0, [%1];" : "=r"(v) : "l"(bar) : "memory");
                } while (v < target);
            }
            __syncthreads();
        }
    }
}

// ---------------------------------------------------------------------------
// skip via bf16 m16n8k16 + ldmatrix (unchanged from R13)
// ---------------------------------------------------------------------------
#define SKIP_SMEM (2 * (18432 + 16384))

__global__ void __launch_bounds__(256, 2) skip_bf16_kernel(const float* __restrict__ x,
                                                           const float* __restrict__ b_skip,
                                                           float* __restrict__ out) {
    extern __shared__ char smc[];
    uint32_t sm32 = smem_u32(smc);

    int tid = threadIdx.x, lane = tid & 31, wid = tid >> 5;
    int OC0 = blockIdx.x * 128;
    int b = blockIdx.y >> 5, y0 = (blockIdx.y & 31) * 2;
    int m0 = (wid & 3) * 32;
    int n0 = (wid >> 2) * 64;
    int nchunks = (OC0 >> 7) + 1;

    const __nv_bfloat16* ob = g_outhb + (long)b * FEAT_ * HH * WW;

    float d[2][8][4];
#pragma unroll
    for (int mt = 0; mt < 2; mt++)
#pragma unroll
        for (int nt = 0; nt < 8; nt++)
#pragma unroll
            for (int i = 0; i < 4; i++) d[mt][nt][i] = 0.f;

    auto issue = [&](int c, int buf) {
        uint32_t ab = sm32 + buf * 34816;
        uint32_t bb = ab + 18432;
        int k0 = c * 64;
#pragma unroll
        for (int j = 0; j < 4; j++) {
            int i = tid + j * 256;
            int row = i >> 3, seg = i & 7;
            CP_ASYNC16(ab + row * 144 + seg * 16,
                       g_wsktb + (long)(OC0 + row) * FEAT_ + k0 + seg * 8);
        }
#pragma unroll
        for (int j = 0; j < 4; j++) {
            int i = tid + j * 256;
            int k = i >> 4, n8 = i & 15, yr = n8 >> 3, w8 = n8 & 7;
            uint32_t da = bb + k * 256 + yr * 128 + ((w8 * 16) ^ ((k & 7) << 4));
            const __nv_bfloat16* sa = ob + ((long)(k0 + k) * HH + y0 + yr) * WW + w8 * 8;
            CP_ASYNC16(da, sa);
        }
    };

    int kfl = lane & 15;
    int swz = (lane & 7) << 4;
    int col8b = (lane & 16) ? 1 : 0;

    issue(0, 0); CP_COMMIT();

    for (int c = 0; c < nchunks; c++) {
        if (c < nchunks - 1) { issue(c + 1, (c + 1) & 1); CP_COMMIT(); CP_WAIT1(); }
        else CP_WAIT0();
        __syncthreads();

        uint32_t ab = sm32 + (c & 1) * 34816;
        uint32_t bb = ab + 18432;
#pragma unroll
        for (int kk = 0; kk < 4; kk++) {
            uint32_t a[2][4];
#pragma unroll
            for (int mt = 0; mt < 2; mt++) {
                uint32_t aaddr = ab + 2 * ((m0 + mt * 16 + (lane & 15)) * 72
                                           + kk * 16 + ((lane >> 4) << 3));
                LDSM_X4(a[mt][0], a[mt][1], a[mt][2], a[mt][3], aaddr);
            }
            uint32_t rowbase = bb + (kk * 16 + kfl) * 256;
#pragma unroll
            for (int j = 0; j < 4; j++) {
                int seg = (n0 >> 3) + j * 2 + col8b;
                uint32_t baddr = rowbase + ((seg >> 3) * 128) + (uint32_t)(((seg & 7) * 16) ^ swz);
                uint32_t b0, b1, b2, b3;
                LDSM_X4T(b0, b1, b2, b3, baddr);
#pragma unroll
                for (int mt = 0; mt < 2; mt++) {
                    mma16(d[mt][j * 2],     a[mt][0], a[mt][1], a[mt][2], a[mt][3], b0, b1);
                    mma16(d[mt][j * 2 + 1], a[mt][0], a[mt][1], a[mt][2], a[mt][3], b2, b3);
                }
            }
        }
        __syncthreads();
    }

    int y = y0 + (n0 >> 6);
#pragma unroll
    for (int mt = 0; mt < 2; mt++) {
        int ocl = OC0 + m0 + mt * 16 + (lane >> 2);
        float bs0 = b_skip[ocl], bs1 = b_skip[ocl + 8];
#pragma unroll
        for (int nt = 0; nt < 8; nt++) {
            int w = nt * 8 + (lane & 3) * 2;
            long off = ((long)(b * CIN_ + ocl) * HH + y) * WW + w;
            float2 xv = *(const float2*)&x[off];
            *(float2*)&out[off] = make_float2(d[mt][nt][0] + xv.x + bs0,
                                              d[mt][nt][1] + xv.y + bs0);
            long off2 = off + (long)8 * HH * WW;
            float2 xv2 = *(const float2*)&x[off2];
            *(float2*)&out[off2] = make_float2(d[mt][nt][2] + xv2.x + bs1,
                                               d[mt][nt][3] + xv2.y + bs1);
        }
    }
}

// ---------------------------------------------------------------------------
extern "C" void kernel_launch(void* const* d_in, const int* in_sizes, int n_in,
                              void* d_out, int out_size) {
    const float* x      = (const float*)d_in[0];
    const float* w_i2s  = (const float*)d_in[1];
    const float* w_s2s  = (const float*)d_in[2];
    const float* w_skip = (const float*)d_in[3];
    const float* b_skip = (const float*)d_in[4];
    float* out = (float*)d_out;

    cudaFuncSetAttribute(i2s_bf16_kernel, cudaFuncAttributeMaxDynamicSharedMemorySize, I2S_SMEM);
    cudaFuncSetAttribute(lstm_scan_mma, cudaFuncAttributeMaxDynamicSharedMemorySize, SCAN_SMEM);
    cudaFuncSetAttribute(skip_bf16_kernel, cudaFuncAttributeMaxDynamicSharedMemorySize, SKIP_SMEM);

    // prep covers ALL merged index spaces: max is NB*CIN_*HH*4 = 1,572,864
    prep_kernel<<<(NB * CIN_ * HH * 4 + 255) / 256, 256>>>(x, w_i2s, w_s2s, w_skip);
    i2s_bf16_kernel<<<dim3(6, NB * 32), 256, I2S_SMEM>>>();
    lstm_scan_mma<<<dim3(24, 4), 512, SCAN_SMEM>>>();
    skip_bf16_kernel<<<dim3(3, NB * 32), 256, SKIP_SMEM>>>(x, b_skip, out);
}

// round 16
// speedup vs baseline: 1.0808x; 1.0808x over previous
#include <cuda_runtime.h>
#include <cuda_bf16.h>
#include <math.h>
#include <stdint.h>

#define NB    16
#define CIN_  384
#define CG    768
#define FEAT_ 192
#define HH    64
#define WW    64
#define HSZ   (NB * FEAT_ * WW)

// Scratch (device globals; no allocations allowed)
__device__ __nv_bfloat16 g_hb[NB * CG * HH * WW];   // shuffled gate inputs, bf16
__device__ __nv_bfloat16 g_Wb2[CG * 768];           // i2s weights [oc'][k=tap*384+ic], bf16, masked
__device__ __nv_bfloat16 g_xb[NB * 2 * CIN_ * HH * WW]; // x, tap-shifted bf16
__device__ __nv_bfloat16 g_w1rb[24 * 3 * 32 * 192]; // s2s weights [ftile][t][ocr][kf], bf16
__device__ __nv_bfloat16 g_wsktb[CIN_ * FEAT_];     // skip weights [co][ci], bf16
__device__ __nv_bfloat16 g_hsh[2][3][HSZ];          // hidden, tap-shifted bf16, double buffered
__device__ __nv_bfloat16 g_outhb[NB * FEAT_ * HH * WW]; // scan outputs, bf16
__device__ unsigned g_rowbar[NB * 32];              // per-bpair row barriers

__device__ __forceinline__ float sigf(float v) { return 1.0f / (1.0f + __expf(-v)); }
__device__ __forceinline__ float tanhfast(float x) {
    float y; asm("tanh.approx.f32 %0, %1;" : "=f"(y) : "f"(x)); return y;
}
__device__ __forceinline__ uint32_t smem_u32(const void* p) {
    uint32_t a;
    asm("{ .reg .u64 t; cvta.to.shared.u64 t, %1; cvt.u32.u64 %0, t; }" : "=r"(a) : "l"(p));
    return a;
}
__device__ __forceinline__ uint32_t pk2(float lo, float hi) {
    uint32_t r; asm("cvt.rn.bf16x2.f32 %0, %1, %2;" : "=r"(r) : "f"(hi), "f"(lo));
    return r;
}
__device__ __forceinline__ float2 upk(uint32_t u) {
    __nv_bfloat162 t = *reinterpret_cast<__nv_bfloat162*>(&u);
    return __bfloat1622float2(t);
}
#define F2U(x) __float_as_uint(x)
#define CP_ASYNC16(dst, src) \
    asm volatile("cp.async.cg.shared.global [%0], [%1], 16;" :: "r"(dst), "l"(src) : "memory")
#define CP_COMMIT() asm volatile("cp.async.commit_group;" ::: "memory")
#define CP_WAIT1()  asm volatile("cp.async.wait_group 1;" ::: "memory")
#define CP_WAIT0()  asm volatile("cp.async.wait_group 0;" ::: "memory")

// bf16 m16n8k16
__device__ __forceinline__ void mma16(float* d, uint32_t a0, uint32_t a1, uint32_t a2, uint32_t a3,
                                      uint32_t b0, uint32_t b1) {
    asm volatile("mma.sync.aligned.m16n8k16.row.col.f32.bf16.bf16.f32 "
                 "{%0,%1,%2,%3}, {%4,%5,%6,%7}, {%8,%9}, {%0,%1,%2,%3};"
                 : "+f"(d[0]), "+f"(d[1]), "+f"(d[2]), "+f"(d[3])
                 : "r"(a0), "r"(a1), "r"(a2), "r"(a3), "r"(b0), "r"(b1));
}
#define LDSM_X4(r0, r1, r2, r3, a) \
    asm volatile("ldmatrix.sync.aligned.m8n8.x4.shared.b16 {%0,%1,%2,%3}, [%4];" \
                 : "=r"(r0), "=r"(r1), "=r"(r2), "=r"(r3) : "r"(a))
#define LDSM_X4T(r0, r1, r2, r3, a) \
    asm volatile("ldmatrix.sync.aligned.m8n8.x4.trans.shared.b16 {%0,%1,%2,%3}, [%4];" \
                 : "=r"(r0), "=r"(r1), "=r"(r2), "=r"(r3) : "r"(a))

// ---------------------------------------------------------------------------
// Weight prep + x tap-shift + state init (merged; launch covers MAX index)
// ---------------------------------------------------------------------------
__global__ void prep_kernel(const float* __restrict__ x,
                            const float* __restrict__ w_i2s,
                            const float* __restrict__ w_s2s,
                            const float* __restrict__ w_skip) {
    int idx = blockIdx.x * blockDim.x + threadIdx.x;
    if (idx < CG * 768) {
        int ocp = idx / 768, k = idx % 768;
        int tap = k / 384, ic = k % 384;
        int q = ocp / 192, p = (ocp % 192) / 64, fl = ocp % 64;
        int c = p * 256 + q * 64 + fl;
        float v = w_i2s[((long)c * CIN_ + ic) * 3 + tap];
        if (tap == 1 && !(p >= (ic / 128))) v = 0.f;
        g_Wb2[idx] = __float2bfloat16(v);
    }
    if (idx < 24 * 3 * 32 * 192) {
        int ftile = idx / 18432;
        int r2 = idx % 18432;
        int t = r2 / 6144;
        int r3 = r2 % 6144;
        int ocr = r3 / 192, kf = r3 % 192;
        int gate = ocr >> 3, j = ocr & 7;
        int oc = gate * FEAT_ + ftile * 8 + j;
        g_w1rb[idx] = __float2bfloat16(w_s2s[((long)oc * FEAT_ + kf) * 3 + t]);
    }
    if (idx < CIN_ * FEAT_) {
        g_wsktb[idx] = __float2bfloat16(w_skip[idx]);
    }
    if (idx < 3 * HSZ / 2) ((uint32_t*)&g_hsh[0][0][0])[idx] = 0u;
    if (idx < NB * 32) g_rowbar[idx] = 0u;

    if (idx < NB * CIN_ * HH * 4) {      // x -> two tap-shifted bf16 copies
        int q = idx & 3, row = idx >> 2;
        int b = row / (CIN_ * HH);
        int rr = row % (CIN_ * HH);
        int ic = rr / HH, y = rr % HH;
        const float* src = x + ((long)(b * CIN_ + ic) * HH + y) * WW + q * 16;
        float v[17];
        v[0] = (q == 0) ? 0.f : src[-1];
#pragma unroll
        for (int j = 0; j < 4; j++) {
            float4 t = *(const float4*)(src + j * 4);
            v[1 + j * 4] = t.x; v[2 + j * 4] = t.y; v[3 + j * 4] = t.z; v[4 + j * 4] = t.w;
        }
        __nv_bfloat16* d0 = g_xb + ((long)((b * 2 + 0) * CIN_ + ic) * HH + y) * WW + q * 16;
        __nv_bfloat16* d1 = g_xb + ((long)((b * 2 + 1) * CIN_ + ic) * HH + y) * WW + q * 16;
        *(uint4*)d0 = make_uint4(pk2(v[0], v[1]), pk2(v[2], v[3]), pk2(v[4], v[5]), pk2(v[6], v[7]));
        *((uint4*)d0 + 1) = make_uint4(pk2(v[8], v[9]), pk2(v[10], v[11]), pk2(v[12], v[13]), pk2(v[14], v[15]));
        *(uint4*)d1 = make_uint4(pk2(v[1], v[2]), pk2(v[3], v[4]), pk2(v[5], v[6]), pk2(v[7], v[8]));
        *((uint4*)d1 + 1) = make_uint4(pk2(v[9], v[10]), pk2(v[11], v[12]), pk2(v[13], v[14]), pk2(v[15], v[16]));
    }
}

// ---------------------------------------------------------------------------
// i2s via bf16 m16n8k16 + ldmatrix; warp tile 32m x 64n; bf16 output.
// ---------------------------------------------------------------------------
#define I2S_SMEM (2 * (18432 + 16384))

__global__ void __launch_bounds__(256, 2) i2s_bf16_kernel() {
    extern __shared__ char smc[];
    uint32_t sm32 = smem_u32(smc);

    int tid = threadIdx.x, lane = tid & 31, wid = tid >> 5;
    int OC0 = blockIdx.x * 128;
    int b = blockIdx.y >> 5, y0 = (blockIdx.y & 31) * 2;
    int m0 = (wid & 3) * 32;
    int n0 = (wid >> 2) * 64;

    const __nv_bfloat16* xbb = g_xb + (long)b * 2 * CIN_ * HH * WW;

    float d[2][8][4];
#pragma unroll
    for (int mt = 0; mt < 2; mt++)
#pragma unroll
        for (int nt = 0; nt < 8; nt++)
#pragma unroll
            for (int i = 0; i < 4; i++) d[mt][nt][i] = 0.f;

    auto issue = [&](int c, int buf) {
        uint32_t ab = sm32 + buf * 34816;
        uint32_t bb = ab + 18432;
        int tap = c / 6, ic0 = (c % 6) * 64;
#pragma unroll
        for (int j = 0; j < 4; j++) {
            int i = tid + j * 256;
            int row = i >> 3, seg = i & 7;
            CP_ASYNC16(ab + row * 144 + seg * 16,
                       g_Wb2 + (long)(OC0 + row) * 768 + c * 64 + seg * 8);
        }
#pragma unroll
        for (int j = 0; j < 4; j++) {
            int i = tid + j * 256;
            int k = i >> 4, n8 = i & 15, yr = n8 >> 3, w8 = n8 & 7;
            uint32_t da = bb + k * 256 + yr * 128 + ((w8 * 16) ^ ((k & 7) << 4));
            const __nv_bfloat16* sa = xbb + ((long)(tap * CIN_ + ic0 + k) * HH + y0 + yr) * WW + w8 * 8;
            CP_ASYNC16(da, sa);
        }
    };

    int kfl = lane & 15;
    int swz = (lane & 7) << 4;
    int col8b = (lane & 16) ? 1 : 0;

    issue(0, 0); CP_COMMIT();

    for (int c = 0; c < 12; c++) {
        if (c < 11) { issue(c + 1, (c + 1) & 1); CP_COMMIT(); CP_WAIT1(); }
        else CP_WAIT0();
        __syncthreads();

        uint32_t ab = sm32 + (c & 1) * 34816;
        uint32_t bb = ab + 18432;
#pragma unroll
        for (int kk = 0; kk < 4; kk++) {
            uint32_t a[2][4];
#pragma unroll
            for (int mt = 0; mt < 2; mt++) {
                uint32_t aaddr = ab + 2 * ((m0 + mt * 16 + (lane & 15)) * 72
                                           + kk * 16 + ((lane >> 4) << 3));
                LDSM_X4(a[mt][0], a[mt][1], a[mt][2], a[mt][3], aaddr);
            }
            uint32_t rowbase = bb + (kk * 16 + kfl) * 256;
#pragma unroll
            for (int j = 0; j < 4; j++) {
                int seg = (n0 >> 3) + j * 2 + col8b;
                uint32_t baddr = rowbase + ((seg >> 3) * 128) + (uint32_t)(((seg & 7) * 16) ^ swz);
                uint32_t b0, b1, b2, b3;
                LDSM_X4T(b0, b1, b2, b3, baddr);
#pragma unroll
                for (int mt = 0; mt < 2; mt++) {
                    mma16(d[mt][j * 2],     a[mt][0], a[mt][1], a[mt][2], a[mt][3], b0, b1);
                    mma16(d[mt][j * 2 + 1], a[mt][0], a[mt][1], a[mt][2], a[mt][3], b2, b3);
                }
            }
        }
        __syncthreads();
    }

    int y = y0 + (n0 >> 6);
#pragma unroll
    for (int mt = 0; mt < 2; mt++) {
        int ocl = OC0 + m0 + mt * 16 + (lane >> 2);
#pragma unroll
        for (int nt = 0; nt < 8; nt++) {
            int w = nt * 8 + (lane & 3) * 2;
            __nv_bfloat16* p0 = &g_hb[(((long)b * CG + ocl) * HH + y) * WW + w];
            *(uint32_t*)p0 = pk2(d[mt][nt][0], d[mt][nt][1]);
            *(uint32_t*)(p0 + (long)8 * HH * WW) = pk2(d[mt][nt][2], d[mt][nt][3]);
        }
    }
}

// ---------------------------------------------------------------------------
// Persistent LSTM scan (R13 verified-best shape): grid (24, 8), 256 thr,
// 2 CTA/SM, per-bpair barrier, 3-stage cp.async ring, early arrive.
// ---------------------------------------------------------------------------
#define SCAN_SMEM (38400 + 3 * 24576)

__global__ void __launch_bounds__(256, 2) lstm_scan_mma() {
    extern __shared__ char smc[];
    uint32_t* wstb_u = (uint32_t*)smc;                       // 9600 uints
    char* hpt = smc + 38400;                                 // 3 x 24576 bytes
    float* sbuf = (float*)hpt;                               // overlay buf0
    uint32_t wstb32 = smem_u32(wstb_u);
    uint32_t hpt32 = smem_u32(hpt);

    int tid = threadIdx.x, lane = tid & 31, wid = tid >> 5;
    int ftile = blockIdx.x, bpair = blockIdx.y;
    int F0 = ftile * 8;
    int m0 = (wid & 1) * 16;
    int wbb = wid >> 2;
    int n0 = ((wid >> 1) & 1) * 32;
    int pbb = tid >> 7, fl = (tid >> 4) & 7, w0 = (tid & 15) * 4;

    {
        const uint32_t* src = (const uint32_t*)&g_w1rb[(long)ftile * 18432];
#pragma unroll
        for (int j = tid; j < 9216; j += 256)
            wstb_u[(j / 96) * 100 + (j % 96)] = src[j];
    }

    float creg[4] = {0.f, 0.f, 0.f, 0.f};
    uint2 hv[4];
    {
        int b = bpair * 2 + pbb;
#pragma unroll
        for (int g = 0; g < 4; g++)
            hv[g] = *(const uint2*)&g_hb[(((long)(b * CG + g * FEAT_ + F0 + fl)) * HH + 0) * WW + w0];
    }
    __syncthreads();

    unsigned* bar = &g_rowbar[bpair * 32];

    int a_row = (m0 + (lane & 15)) * 200 + ((lane >> 4) << 3);
    int kfl  = (lane & 7) + (lane & 8);
    int swz  = (lane & 7) << 4;
    int col8 = (lane & 16) ? 8 : 0;

    for (int y = 0; y < HH; y++) {
        const __nv_bfloat16* hsrc = &g_hsh[y & 1][0][0];

        auto issue_chunk = [&](int ch, int buf) {
            int f0k = ch * 32;
            uint32_t dbase = hpt32 + buf * 24576;
#pragma unroll
            for (int j = 0; j < 6; j++) {
                int i = tid + j * 256;
                int t = i >> 9, r = i & 511, bb = r >> 8, kf = (r >> 3) & 31, w4 = r & 7;
                uint32_t da = dbase + (((t * 2 + bb) * 32 + kf) << 7)
                            + ((w4 * 16) ^ ((kf & 7) << 4));
                const __nv_bfloat16* sa = hsrc + (long)t * HSZ
                            + ((bpair * 2 + bb) * FEAT_ + f0k + kf) * WW + w4 * 8;
                CP_ASYNC16(da, sa);
            }
        };

        float d[4][4];
#pragma unroll
        for (int nt = 0; nt < 4; nt++)
#pragma unroll
            for (int i = 0; i < 4; i++) d[nt][i] = 0.f;

        issue_chunk(0, 0); CP_COMMIT();
        issue_chunk(1, 1); CP_COMMIT();

#pragma unroll
        for (int ch = 0; ch < 6; ch++) {
            if (ch < 5) CP_WAIT1(); else CP_WAIT0();
            __syncthreads();
            if (ch < 4) { issue_chunk(ch + 2, (ch + 2) % 3); CP_COMMIT(); }

            uint32_t hb = hpt32 + (ch % 3) * 24576;
            int kbase = ch * 32;
#pragma unroll
            for (int t = 0; t < 3; t++) {
#pragma unroll
                for (int kk = 0; kk < 2; kk++) {
                    uint32_t a0, a1, a2, a3;
                    uint32_t aaddr = wstb32 + 2 * (t * 6400 + a_row + kbase + kk * 16);
                    LDSM_X4(a0, a1, a2, a3, aaddr);
                    uint32_t rowoff = (uint32_t)(((t * 2 + wbb) * 32 + kk * 16 + kfl) << 7);
#pragma unroll
                    for (int nt2 = 0; nt2 < 2; nt2++) {
                        uint32_t b0, b1, b2, b3;
                        uint32_t baddr = hb + rowoff
                                       + ((uint32_t)((n0 + nt2 * 16 + col8) * 2) ^ (uint32_t)swz);
                        LDSM_X4T(b0, b1, b2, b3, baddr);
                        mma16(d[nt2 * 2],     a0, a1, a2, a3, b0, b1);
                        mma16(d[nt2 * 2 + 1], a0, a1, a2, a3, b2, b3);
                    }
                }
            }
        }

#pragma unroll
        for (int nt = 0; nt < 4; nt++) {
            int r = m0 + (lane >> 2);
            int cc = n0 + nt * 8 + (lane & 3) * 2;
            *(float2*)&sbuf[wbb * 2176 + r * 68 + cc] = make_float2(d[nt][0], d[nt][1]);
            *(float2*)&sbuf[wbb * 2176 + (r + 8) * 68 + cc] = make_float2(d[nt][2], d[nt][3]);
        }
        __syncthreads();

        int b = bpair * 2 + pbb;
        float hn[4];
        {
            float* sb = sbuf + pbb * 2176;
            float4 ov = *(const float4*)&sb[fl * 68 + w0];
            float4 fv = *(const float4*)&sb[(8 + fl) * 68 + w0];
            float4 iv = *(const float4*)&sb[(16 + fl) * 68 + w0];
            float4 gv = *(const float4*)&sb[(24 + fl) * 68 + w0];
            float hva[4][4];
#pragma unroll
            for (int g = 0; g < 4; g++) {
                float2 p0 = upk(hv[g].x), p1 = upk(hv[g].y);
                hva[g][0] = p0.x; hva[g][1] = p0.y; hva[g][2] = p1.x; hva[g][3] = p1.y;
            }
            float so[4] = {sigf(ov.x + hva[0][0]), sigf(ov.y + hva[0][1]),
                           sigf(ov.z + hva[0][2]), sigf(ov.w + hva[0][3])};
            float sf[4] = {sigf(fv.x + hva[1][0]), sigf(fv.y + hva[1][1]),
                           sigf(fv.z + hva[1][2]), sigf(fv.w + hva[1][3])};
            float si[4] = {sigf(iv.x + hva[2][0]), sigf(iv.y + hva[2][1]),
                           sigf(iv.z + hva[2][2]), sigf(iv.w + hva[2][3])};
            float sg[4] = {sigf(gv.x + hva[3][0]), sigf(gv.y + hva[3][1]),
                           sigf(gv.z + hva[3][2]), sigf(gv.w + hva[3][3])};
#pragma unroll
            for (int i = 0; i < 4; i++) {
                creg[i] = sf[i] * creg[i] + si[i] * sg[i];
                hn[i] = so[i] * tanhfast(creg[i]);
            }
            float lft = __shfl_up_sync(0xffffffffu, hn[3], 1);
            float rgt = __shfl_down_sync(0xffffffffu, hn[0], 1);
            if ((tid & 15) == 0) lft = 0.f;
            if ((tid & 15) == 15) rgt = 0.f;

            long fbase = ((long)(b * FEAT_ + F0 + fl)) * WW + w0;
            __nv_bfloat16* hbd = &g_hsh[(y & 1) ^ 1][0][0];
            *(uint2*)(hbd + fbase)           = make_uint2(pk2(lft, hn[0]), pk2(hn[1], hn[2]));
            *(uint2*)(hbd + HSZ + fbase)     = make_uint2(pk2(hn[0], hn[1]), pk2(hn[2], hn[3]));
            *(uint2*)(hbd + 2 * HSZ + fbase) = make_uint2(pk2(hn[1], hn[2]), pk2(hn[3], rgt));
        }
        __syncthreads();                 // all h-state stores done; sbuf consumed

        // arrive EARLY, then overlap outhb store + next-row prefetch with peers
        if (tid == 0 && y < HH - 1) {
            asm volatile("red.release.gpu.global.add.u32 [%0], %1;" :: "l"(bar), "r"(1u) : "memory");
        }
        {
            __nv_bfloat16* op = &g_outhb[((b * FEAT_ + F0 + fl) * HH + y) * WW + w0];
            *(uint2*)op = make_uint2(pk2(hn[0], hn[1]), pk2(hn[2], hn[3]));
        }
        if (y < HH - 1) {
#pragma unroll
            for (int g = 0; g < 4; g++)
                hv[g] = *(const uint2*)&g_hb[(((long)(b * CG + g * FEAT_ + F0 + fl)) * HH + (y + 1)) * WW + w0];
            if (tid == 0) {
                unsigned target = 24u * (unsigned)(y + 1);
                unsigned v;
                do {
                    asm volatile("ld.acquire.gpu.global.u32 %0, [%1];" : "=r"(v) : "l"(bar) : "memory");
                } while (v < target);
            }
            __syncthreads();
        }
    }
}

// ---------------------------------------------------------------------------
// skip via bf16 m16n8k16 + ldmatrix
// ---------------------------------------------------------------------------
#define SKIP_SMEM (2 * (18432 + 16384))

__global__ void __launch_bounds__(256, 2) skip_bf16_kernel(const float* __restrict__ x,
                                                           const float* __restrict__ b_skip,
                                                           float* __restrict__ out) {
    extern __shared__ char smc[];
    uint32_t sm32 = smem_u32(smc);

    int tid = threadIdx.x, lane = tid & 31, wid = tid >> 5;
    int OC0 = blockIdx.x * 128;
    int b = blockIdx.y >> 5, y0 = (blockIdx.y & 31) * 2;
    int m0 = (wid & 3) * 32;
    int n0 = (wid >> 2) * 64;
    int nchunks = (OC0 >> 7) + 1;

    const __nv_bfloat16* ob = g_outhb + (long)b * FEAT_ * HH * WW;

    float d[2][8][4];
#pragma unroll
    for (int mt = 0; mt < 2; mt++)
#pragma unroll
        for (int nt = 0; nt < 8; nt++)
#pragma unroll
            for (int i = 0; i < 4; i++) d[mt][nt][i] = 0.f;

    auto issue = [&](int c, int buf) {
        uint32_t ab = sm32 + buf * 34816;
        uint32_t bb = ab + 18432;
        int k0 = c * 64;
#pragma unroll
        for (int j = 0; j < 4; j++) {
            int i = tid + j * 256;
            int row = i >> 3, seg = i & 7;
            CP_ASYNC16(ab + row * 144 + seg * 16,
                       g_wsktb + (long)(OC0 + row) * FEAT_ + k0 + seg * 8);
        }
#pragma unroll
        for (int j = 0; j < 4; j++) {
            int i = tid + j * 256;
            int k = i >> 4, n8 = i & 15, yr = n8 >> 3, w8 = n8 & 7;
            uint32_t da = bb + k * 256 + yr * 128 + ((w8 * 16) ^ ((k & 7) << 4));
            const __nv_bfloat16* sa = ob + ((long)(k0 + k) * HH + y0 + yr) * WW + w8 * 8;
            CP_ASYNC16(da, sa);
        }
    };

    int kfl = lane & 15;
    int swz = (lane & 7) << 4;
    int col8b = (lane & 16) ? 1 : 0;

    issue(0, 0); CP_COMMIT();

    for (int c = 0; c < nchunks; c++) {
        if (c < nchunks - 1) { issue(c + 1, (c + 1) & 1); CP_COMMIT(); CP_WAIT1(); }
        else CP_WAIT0();
        __syncthreads();

        uint32_t ab = sm32 + (c & 1) * 34816;
        uint32_t bb = ab + 18432;
#pragma unroll
        for (int kk = 0; kk < 4; kk++) {
            uint32_t a[2][4];
#pragma unroll
            for (int mt = 0; mt < 2; mt++) {
                uint32_t aaddr = ab + 2 * ((m0 + mt * 16 + (lane & 15)) * 72
                                           + kk * 16 + ((lane >> 4) << 3));
                LDSM_X4(a[mt][0], a[mt][1], a[mt][2], a[mt][3], aaddr);
            }
            uint32_t rowbase = bb + (kk * 16 + kfl) * 256;
#pragma unroll
            for (int j = 0; j < 4; j++) {
                int seg = (n0 >> 3) + j * 2 + col8b;
                uint32_t baddr = rowbase + ((seg >> 3) * 128) + (uint32_t)(((seg & 7) * 16) ^ swz);
                uint32_t b0, b1, b2, b3;
                LDSM_X4T(b0, b1, b2, b3, baddr);
#pragma unroll
                for (int mt = 0; mt < 2; mt++) {
                    mma16(d[mt][j * 2],     a[mt][0], a[mt][1], a[mt][2], a[mt][3], b0, b1);
                    mma16(d[mt][j * 2 + 1], a[mt][0], a[mt][1], a[mt][2], a[mt][3], b2, b3);
                }
            }
        }
        __syncthreads();
    }

    int y = y0 + (n0 >> 6);
#pragma unroll
    for (int mt = 0; mt < 2; mt++) {
        int ocl = OC0 + m0 + mt * 16 + (lane >> 2);
        float bs0 = b_skip[ocl], bs1 = b_skip[ocl + 8];
#pragma unroll
        for (int nt = 0; nt < 8; nt++) {
            int w = nt * 8 + (lane & 3) * 2;
            long off = ((long)(b * CIN_ + ocl) * HH + y) * WW + w;
            float2 xv = *(const float2*)&x[off];
            *(float2*)&out[off] = make_float2(d[mt][nt][0] + xv.x + bs0,
                                              d[mt][nt][1] + xv.y + bs0);
            long off2 = off + (long)8 * HH * WW;
            float2 xv2 = *(const float2*)&x[off2];
            *(float2*)&out[off2] = make_float2(d[mt][nt][2] + xv2.x + bs1,
                                               d[mt][nt][3] + xv2.y + bs1);
        }
    }
}

// ---------------------------------------------------------------------------
extern "C" void kernel_launch(void* const* d_in, const int* in_sizes, int n_in,
                              void* d_out, int out_size) {
    const float* x      = (const float*)d_in[0];
    const float* w_i2s  = (const float*)d_in[1];
    const float* w_s2s  = (const float*)d_in[2];
    const float* w_skip = (const float*)d_in[3];
    const float* b_skip = (const float*)d_in[4];
    float* out = (float*)d_out;

    cudaFuncSetAttribute(i2s_bf16_kernel, cudaFuncAttributeMaxDynamicSharedMemorySize, I2S_SMEM);
    cudaFuncSetAttribute(lstm_scan_mma, cudaFuncAttributeMaxDynamicSharedMemorySize, SCAN_SMEM);
    cudaFuncSetAttribute(skip_bf16_kernel, cudaFuncAttributeMaxDynamicSharedMemorySize, SKIP_SMEM);

    // prep covers ALL merged index spaces: max is NB*CIN_*HH*4 = 1,572,864
    prep_kernel<<<(NB * CIN_ * HH * 4 + 255) / 256, 256>>>(x, w_i2s, w_s2s, w_skip);
    i2s_bf16_kernel<<<dim3(6, NB * 32), 256, I2S_SMEM>>>();
    lstm_scan_mma<<<dim3(24, 8), 256, SCAN_SMEM>>>();
    skip_bf16_kernel<<<dim3(3, NB * 32), 256, SKIP_SMEM>>>(x, b_skip, out);
}

// round 17
// speedup vs baseline: 1.1272x; 1.0429x over previous
#include <cuda_runtime.h>
#include <cuda_bf16.h>
#include <math.h>
#include <stdint.h>

#define NB    16
#define CIN_  384
#define CG    768
#define FEAT_ 192
#define HH    64
#define WW    64
#define HSZ   (NB * FEAT_ * WW)

// Scratch (device globals; no allocations allowed)
__device__ __nv_bfloat16 g_hb[NB * CG * HH * WW];   // shuffled gate inputs, bf16
__device__ __nv_bfloat16 g_Wb2[CG * 768];           // i2s weights [ocpp][k=tap*384+ic], p-grouped
__device__ __nv_bfloat16 g_xb[NB * 2 * CIN_ * HH * WW]; // x, tap-shifted bf16
__device__ __nv_bfloat16 g_w1rb[24 * 3 * 32 * 192]; // s2s weights [ftile][t][ocr][kf], bf16
__device__ __nv_bfloat16 g_wsktb[CIN_ * FEAT_];     // skip weights [co][ci], bf16
__device__ __nv_bfloat16 g_hsh[2][3][HSZ];          // hidden, tap-shifted bf16, double buffered
__device__ __nv_bfloat16 g_outhb[NB * FEAT_ * HH * WW]; // scan outputs, bf16
__device__ unsigned g_rowbar[NB * 32];              // per-bpair row barriers

__device__ __forceinline__ float sigf(float v) { return 1.0f / (1.0f + __expf(-v)); }
__device__ __forceinline__ float tanhfast(float x) {
    float y; asm("tanh.approx.f32 %0, %1;" : "=f"(y) : "f"(x)); return y;
}
__device__ __forceinline__ uint32_t smem_u32(const void* p) {
    uint32_t a;
    asm("{ .reg .u64 t; cvta.to.shared.u64 t, %1; cvt.u32.u64 %0, t; }" : "=r"(a) : "l"(p));
    return a;
}
__device__ __forceinline__ uint32_t pk2(float lo, float hi) {
    uint32_t r; asm("cvt.rn.bf16x2.f32 %0, %1, %2;" : "=r"(r) : "f"(hi), "f"(lo));
    return r;
}
__device__ __forceinline__ float2 upk(uint32_t u) {
    __nv_bfloat162 t = *reinterpret_cast<__nv_bfloat162*>(&u);
    return __bfloat1622float2(t);
}
#define F2U(x) __float_as_uint(x)
#define CP_ASYNC16(dst, src) \
    asm volatile("cp.async.cg.shared.global [%0], [%1], 16;" :: "r"(dst), "l"(src) : "memory")
#define CP_COMMIT() asm volatile("cp.async.commit_group;" ::: "memory")
#define CP_WAIT1()  asm volatile("cp.async.wait_group 1;" ::: "memory")
#define CP_WAIT0()  asm volatile("cp.async.wait_group 0;" ::: "memory")

// bf16 m16n8k16
__device__ __forceinline__ void mma16(float* d, uint32_t a0, uint32_t a1, uint32_t a2, uint32_t a3,
                                      uint32_t b0, uint32_t b1) {
    asm volatile("mma.sync.aligned.m16n8k16.row.col.f32.bf16.bf16.f32 "
                 "{%0,%1,%2,%3}, {%4,%5,%6,%7}, {%8,%9}, {%0,%1,%2,%3};"
                 : "+f"(d[0]), "+f"(d[1]), "+f"(d[2]), "+f"(d[3])
                 : "r"(a0), "r"(a1), "r"(a2), "r"(a3), "r"(b0), "r"(b1));
}
#define LDSM_X4(r0, r1, r2, r3, a) \
    asm volatile("ldmatrix.sync.aligned.m8n8.x4.shared.b16 {%0,%1,%2,%3}, [%4];" \
                 : "=r"(r0), "=r"(r1), "=r"(r2), "=r"(r3) : "r"(a))
#define LDSM_X4T(r0, r1, r2, r3, a) \
    asm volatile("ldmatrix.sync.aligned.m8n8.x4.trans.shared.b16 {%0,%1,%2,%3}, [%4];" \
                 : "=r"(r0), "=r"(r1), "=r"(r2), "=r"(r3) : "r"(a))

// ---------------------------------------------------------------------------
// Weight prep + x tap-shift + state init. i2s weights now p-grouped:
// ocpp = pgrp*256 + q*64 + fl  <->  original c = pgrp*256 + q*64 + fl,
// shuffled cp = q*192 + pgrp*64 + fl. tap1 zero beyond ic >= 128*(pgrp+1).
// ---------------------------------------------------------------------------
__global__ void prep_kernel(const float* __restrict__ x,
                            const float* __restrict__ w_i2s,
                            const float* __restrict__ w_s2s,
                            const float* __restrict__ w_skip) {
    int idx = blockIdx.x * blockDim.x + threadIdx.x;
    if (idx < CG * 768) {
        int ocpp = idx / 768, k = idx % 768;
        int tap = k / 384, ic = k % 384;
        int pgrp = ocpp >> 8, r = ocpp & 255, q = r >> 6, fl = r & 63;
        int c = pgrp * 256 + q * 64 + fl;          // original channel (pre-shuffle)
        float v = w_i2s[((long)c * CIN_ + ic) * 3 + tap];
        if (tap == 1 && !(pgrp >= (ic / 128))) v = 0.f;
        g_Wb2[idx] = __float2bfloat16(v);
    }
    if (idx < 24 * 3 * 32 * 192) {
        int ftile = idx / 18432;
        int r2 = idx % 18432;
        int t = r2 / 6144;
        int r3 = r2 % 6144;
        int ocr = r3 / 192, kf = r3 % 192;
        int gate = ocr >> 3, j = ocr & 7;
        int oc = gate * FEAT_ + ftile * 8 + j;
        g_w1rb[idx] = __float2bfloat16(w_s2s[((long)oc * FEAT_ + kf) * 3 + t]);
    }
    if (idx < CIN_ * FEAT_) {
        g_wsktb[idx] = __float2bfloat16(w_skip[idx]);
    }
    if (idx < 3 * HSZ / 2) ((uint32_t*)&g_hsh[0][0][0])[idx] = 0u;
    if (idx < NB * 32) g_rowbar[idx] = 0u;

    if (idx < NB * CIN_ * HH * 4) {      // x -> two tap-shifted bf16 copies
        int q = idx & 3, row = idx >> 2;
        int b = row / (CIN_ * HH);
        int rr = row % (CIN_ * HH);
        int ic = rr / HH, y = rr % HH;
        const float* src = x + ((long)(b * CIN_ + ic) * HH + y) * WW + q * 16;
        float v[17];
        v[0] = (q == 0) ? 0.f : src[-1];
#pragma unroll
        for (int j = 0; j < 4; j++) {
            float4 t = *(const float4*)(src + j * 4);
            v[1 + j * 4] = t.x; v[2 + j * 4] = t.y; v[3 + j * 4] = t.z; v[4 + j * 4] = t.w;
        }
        __nv_bfloat16* d0 = g_xb + ((long)((b * 2 + 0) * CIN_ + ic) * HH + y) * WW + q * 16;
        __nv_bfloat16* d1 = g_xb + ((long)((b * 2 + 1) * CIN_ + ic) * HH + y) * WW + q * 16;
        *(uint4*)d0 = make_uint4(pk2(v[0], v[1]), pk2(v[2], v[3]), pk2(v[4], v[5]), pk2(v[6], v[7]));
        *((uint4*)d0 + 1) = make_uint4(pk2(v[8], v[9]), pk2(v[10], v[11]), pk2(v[12], v[13]), pk2(v[14], v[15]));
        *(uint4*)d1 = make_uint4(pk2(v[1], v[2]), pk2(v[3], v[4]), pk2(v[5], v[6]), pk2(v[7], v[8]));
        *((uint4*)d1 + 1) = make_uint4(pk2(v[9], v[10]), pk2(v[11], v[12]), pk2(v[13], v[14]), pk2(v[15], v[16]));
    }
}

// ---------------------------------------------------------------------------
// i2s via bf16 m16n8k16 + ldmatrix; p-grouped M blocks with variable K:
// block pgrp = blockIdx.x>>1, nchunks = 6 (tap0) + 2*(pgrp+1) (tap1).
// ---------------------------------------------------------------------------
#define I2S_SMEM (2 * (18432 + 16384))

__global__ void __launch_bounds__(256, 2) i2s_bf16_kernel() {
    extern __shared__ char smc[];
    uint32_t sm32 = smem_u32(smc);

    int tid = threadIdx.x, lane = tid & 31, wid = tid >> 5;
    int OC0 = blockIdx.x * 128;
    int pgrp = blockIdx.x >> 1;
    int nch = 6 + 2 * (pgrp + 1);        // 8 / 10 / 12
    int b = blockIdx.y >> 5, y0 = (blockIdx.y & 31) * 2;
    int m0 = (wid & 3) * 32;
    int n0 = (wid >> 2) * 64;

    const __nv_bfloat16* xbb = g_xb + (long)b * 2 * CIN_ * HH * WW;

    float d[2][8][4];
#pragma unroll
    for (int mt = 0; mt < 2; mt++)
#pragma unroll
        for (int nt = 0; nt < 8; nt++)
#pragma unroll
            for (int i = 0; i < 4; i++) d[mt][nt][i] = 0.f;

    auto issue = [&](int c, int buf) {
        uint32_t ab = sm32 + buf * 34816;
        uint32_t bb = ab + 18432;
        int tap = c / 6, ic0 = (c % 6) * 64;   // k = c*64 contiguous in g_Wb2
#pragma unroll
        for (int j = 0; j < 4; j++) {
            int i = tid + j * 256;
            int row = i >> 3, seg = i & 7;
            CP_ASYNC16(ab + row * 144 + seg * 16,
                       g_Wb2 + (long)(OC0 + row) * 768 + c * 64 + seg * 8);
        }
#pragma unroll
        for (int j = 0; j < 4; j++) {
            int i = tid + j * 256;
            int k = i >> 4, n8 = i & 15, yr = n8 >> 3, w8 = n8 & 7;
            uint32_t da = bb + k * 256 + yr * 128 + ((w8 * 16) ^ ((k & 7) << 4));
            const __nv_bfloat16* sa = xbb + ((long)(tap * CIN_ + ic0 + k) * HH + y0 + yr) * WW + w8 * 8;
            CP_ASYNC16(da, sa);
        }
    };

    int kfl = lane & 15;
    int swz = (lane & 7) << 4;
    int col8b = (lane & 16) ? 1 : 0;

    issue(0, 0); CP_COMMIT();

    for (int c = 0; c < nch; c++) {
        if (c < nch - 1) { issue(c + 1, (c + 1) & 1); CP_COMMIT(); CP_WAIT1(); }
        else CP_WAIT0();
        __syncthreads();

        uint32_t ab = sm32 + (c & 1) * 34816;
        uint32_t bb = ab + 18432;
#pragma unroll
        for (int kk = 0; kk < 4; kk++) {
            uint32_t a[2][4];
#pragma unroll
            for (int mt = 0; mt < 2; mt++) {
                uint32_t aaddr = ab + 2 * ((m0 + mt * 16 + (lane & 15)) * 72
                                           + kk * 16 + ((lane >> 4) << 3));
                LDSM_X4(a[mt][0], a[mt][1], a[mt][2], a[mt][3], aaddr);
            }
            uint32_t rowbase = bb + (kk * 16 + kfl) * 256;
#pragma unroll
            for (int j = 0; j < 4; j++) {
                int seg = (n0 >> 3) + j * 2 + col8b;
                uint32_t baddr = rowbase + ((seg >> 3) * 128) + (uint32_t)(((seg & 7) * 16) ^ swz);
                uint32_t b0, b1, b2, b3;
                LDSM_X4T(b0, b1, b2, b3, baddr);
#pragma unroll
                for (int mt = 0; mt < 2; mt++) {
                    mma16(d[mt][j * 2],     a[mt][0], a[mt][1], a[mt][2], a[mt][3], b0, b1);
                    mma16(d[mt][j * 2 + 1], a[mt][0], a[mt][1], a[mt][2], a[mt][3], b2, b3);
                }
            }
        }
        __syncthreads();
    }

    // epilogue: un-permute p-grouped rows -> shuffled channel cp = q*192+pgrp*64+fl
    int y = y0 + (n0 >> 6);
#pragma unroll
    for (int mt = 0; mt < 2; mt++) {
        int ocpp = OC0 + m0 + mt * 16 + (lane >> 2);
        int q = (ocpp >> 6) & 3, fl = ocpp & 63;
        int cp = q * 192 + pgrp * 64 + fl;           // fl <= 55 here, so cp+8 = same q block
#pragma unroll
        for (int nt = 0; nt < 8; nt++) {
            int w = nt * 8 + (lane & 3) * 2;
            __nv_bfloat16* p0 = &g_hb[(((long)b * CG + cp) * HH + y) * WW + w];
            *(uint32_t*)p0 = pk2(d[mt][nt][0], d[mt][nt][1]);
            *(uint32_t*)(p0 + (long)8 * HH * WW) = pk2(d[mt][nt][2], d[mt][nt][3]);
        }
    }
}

// ---------------------------------------------------------------------------
// Persistent LSTM scan (R13 verified-best shape): grid (24, 8), 256 thr,
// 2 CTA/SM, per-bpair barrier, 3-stage cp.async ring, early arrive.
// ---------------------------------------------------------------------------
#define SCAN_SMEM (38400 + 3 * 24576)

__global__ void __launch_bounds__(256, 2) lstm_scan_mma() {
    extern __shared__ char smc[];
    uint32_t* wstb_u = (uint32_t*)smc;                       // 9600 uints
    char* hpt = smc + 38400;                                 // 3 x 24576 bytes
    float* sbuf = (float*)hpt;                               // overlay buf0
    uint32_t wstb32 = smem_u32(wstb_u);
    uint32_t hpt32 = smem_u32(hpt);

    int tid = threadIdx.x, lane = tid & 31, wid = tid >> 5;
    int ftile = blockIdx.x, bpair = blockIdx.y;
    int F0 = ftile * 8;
    int m0 = (wid & 1) * 16;
    int wbb = wid >> 2;
    int n0 = ((wid >> 1) & 1) * 32;
    int pbb = tid >> 7, fl = (tid >> 4) & 7, w0 = (tid & 15) * 4;

    {
        const uint32_t* src = (const uint32_t*)&g_w1rb[(long)ftile * 18432];
#pragma unroll
        for (int j = tid; j < 9216; j += 256)
            wstb_u[(j / 96) * 100 + (j % 96)] = src[j];
    }

    float creg[4] = {0.f, 0.f, 0.f, 0.f};
    uint2 hv[4];
    {
        int b = bpair * 2 + pbb;
#pragma unroll
        for (int g = 0; g < 4; g++)
            hv[g] = *(const uint2*)&g_hb[(((long)(b * CG + g * FEAT_ + F0 + fl)) * HH + 0) * WW + w0];
    }
    __syncthreads();

    unsigned* bar = &g_rowbar[bpair * 32];

    int a_row = (m0 + (lane & 15)) * 200 + ((lane >> 4) << 3);
    int kfl  = (lane & 7) + (lane & 8);
    int swz  = (lane & 7) << 4;
    int col8 = (lane & 16) ? 8 : 0;

    for (int y = 0; y < HH; y++) {
        const __nv_bfloat16* hsrc = &g_hsh[y & 1][0][0];

        auto issue_chunk = [&](int ch, int buf) {
            int f0k = ch * 32;
            uint32_t dbase = hpt32 + buf * 24576;
#pragma unroll
            for (int j = 0; j < 6; j++) {
                int i = tid + j * 256;
                int t = i >> 9, r = i & 511, bb = r >> 8, kf = (r >> 3) & 31, w4 = r & 7;
                uint32_t da = dbase + (((t * 2 + bb) * 32 + kf) << 7)
                            + ((w4 * 16) ^ ((kf & 7) << 4));
                const __nv_bfloat16* sa = hsrc + (long)t * HSZ
                            + ((bpair * 2 + bb) * FEAT_ + f0k + kf) * WW + w4 * 8;
                CP_ASYNC16(da, sa);
            }
        };

        float d[4][4];
#pragma unroll
        for (int nt = 0; nt < 4; nt++)
#pragma unroll
            for (int i = 0; i < 4; i++) d[nt][i] = 0.f;

        issue_chunk(0, 0); CP_COMMIT();
        issue_chunk(1, 1); CP_COMMIT();

#pragma unroll
        for (int ch = 0; ch < 6; ch++) {
            if (ch < 5) CP_WAIT1(); else CP_WAIT0();
            __syncthreads();
            if (ch < 4) { issue_chunk(ch + 2, (ch + 2) % 3); CP_COMMIT(); }

            uint32_t hb = hpt32 + (ch % 3) * 24576;
            int kbase = ch * 32;
#pragma unroll
            for (int t = 0; t < 3; t++) {
#pragma unroll
                for (int kk = 0; kk < 2; kk++) {
                    uint32_t a0, a1, a2, a3;
                    uint32_t aaddr = wstb32 + 2 * (t * 6400 + a_row + kbase + kk * 16);
                    LDSM_X4(a0, a1, a2, a3, aaddr);
                    uint32_t rowoff = (uint32_t)(((t * 2 + wbb) * 32 + kk * 16 + kfl) << 7);
#pragma unroll
                    for (int nt2 = 0; nt2 < 2; nt2++) {
                        uint32_t b0, b1, b2, b3;
                        uint32_t baddr = hb + rowoff
                                       + ((uint32_t)((n0 + nt2 * 16 + col8) * 2) ^ (uint32_t)swz);
                        LDSM_X4T(b0, b1, b2, b3, baddr);
                        mma16(d[nt2 * 2],     a0, a1, a2, a3, b0, b1);
                        mma16(d[nt2 * 2 + 1], a0, a1, a2, a3, b2, b3);
                    }
                }
            }
        }

#pragma unroll
        for (int nt = 0; nt < 4; nt++) {
            int r = m0 + (lane >> 2);
            int cc = n0 + nt * 8 + (lane & 3) * 2;
            *(float2*)&sbuf[wbb * 2176 + r * 68 + cc] = make_float2(d[nt][0], d[nt][1]);
            *(float2*)&sbuf[wbb * 2176 + (r + 8) * 68 + cc] = make_float2(d[nt][2], d[nt][3]);
        }
        __syncthreads();

        int b = bpair * 2 + pbb;
        float hn[4];
        {
            float* sb = sbuf + pbb * 2176;
            float4 ov = *(const float4*)&sb[fl * 68 + w0];
            float4 fv = *(const float4*)&sb[(8 + fl) * 68 + w0];
            float4 iv = *(const float4*)&sb[(16 + fl) * 68 + w0];
            float4 gv = *(const float4*)&sb[(24 + fl) * 68 + w0];
            float hva[4][4];
#pragma unroll
            for (int g = 0; g < 4; g++) {
                float2 p0 = upk(hv[g].x), p1 = upk(hv[g].y);
                hva[g][0] = p0.x; hva[g][1] = p0.y; hva[g][2] = p1.x; hva[g][3] = p1.y;
            }
            float so[4] = {sigf(ov.x + hva[0][0]), sigf(ov.y + hva[0][1]),
                           sigf(ov.z + hva[0][2]), sigf(ov.w + hva[0][3])};
            float sf[4] = {sigf(fv.x + hva[1][0]), sigf(fv.y + hva[1][1]),
                           sigf(fv.z + hva[1][2]), sigf(fv.w + hva[1][3])};
            float si[4] = {sigf(iv.x + hva[2][0]), sigf(iv.y + hva[2][1]),
                           sigf(iv.z + hva[2][2]), sigf(iv.w + hva[2][3])};
            float sg[4] = {sigf(gv.x + hva[3][0]), sigf(gv.y + hva[3][1]),
                           sigf(gv.z + hva[3][2]), sigf(gv.w + hva[3][3])};
#pragma unroll
            for (int i = 0; i < 4; i++) {
                creg[i] = sf[i] * creg[i] + si[i] * sg[i];
                hn[i] = so[i] * tanhfast(creg[i]);
            }
            float lft = __shfl_up_sync(0xffffffffu, hn[3], 1);
            float rgt = __shfl_down_sync(0xffffffffu, hn[0], 1);
            if ((tid & 15) == 0) lft = 0.f;
            if ((tid & 15) == 15) rgt = 0.f;

            long fbase = ((long)(b * FEAT_ + F0 + fl)) * WW + w0;
            __nv_bfloat16* hbd = &g_hsh[(y & 1) ^ 1][0][0];
            *(uint2*)(hbd + fbase)           = make_uint2(pk2(lft, hn[0]), pk2(hn[1], hn[2]));
            *(uint2*)(hbd + HSZ + fbase)     = make_uint2(pk2(hn[0], hn[1]), pk2(hn[2], hn[3]));
            *(uint2*)(hbd + 2 * HSZ + fbase) = make_uint2(pk2(hn[1], hn[2]), pk2(hn[3], rgt));
        }
        __syncthreads();                 // all h-state stores done; sbuf consumed

        // arrive EARLY, then overlap outhb store + next-row prefetch with peers
        if (tid == 0 && y < HH - 1) {
            asm volatile("red.release.gpu.global.add.u32 [%0], %1;" :: "l"(bar), "r"(1u) : "memory");
        }
        {
            __nv_bfloat16* op = &g_outhb[((b * FEAT_ + F0 + fl) * HH + y) * WW + w0];
            *(uint2*)op = make_uint2(pk2(hn[0], hn[1]), pk2(hn[2], hn[3]));
        }
        if (y < HH - 1) {
#pragma unroll
            for (int g = 0; g < 4; g++)
                hv[g] = *(const uint2*)&g_hb[(((long)(b * CG + g * FEAT_ + F0 + fl)) * HH + (y + 1)) * WW + w0];
            if (tid == 0) {
                unsigned target = 24u * (unsigned)(y + 1);
                unsigned v;
                do {
                    asm volatile("ld.acquire.gpu.global.u32 %0, [%1];" : "=r"(v) : "l"(bar) : "memory");
                } while (v < target);
            }
            __syncthreads();
        }
    }
}

// ---------------------------------------------------------------------------
// skip via bf16 m16n8k16 + ldmatrix (unchanged)
// ---------------------------------------------------------------------------
#define SKIP_SMEM (2 * (18432 + 16384))

__global__ void __launch_bounds__(256, 2) skip_bf16_kernel(const float* __restrict__ x,
                                                           const float* __restrict__ b_skip,
                                                           float* __restrict__ out) {
    extern __shared__ char smc[];
    uint32_t sm32 = smem_u32(smc);

    int tid = threadIdx.x, lane = tid & 31, wid = tid >> 5;
    int OC0 = blockIdx.x * 128;
    int b = blockIdx.y >> 5, y0 = (blockIdx.y & 31) * 2;
    int m0 = (wid & 3) * 32;
    int n0 = (wid >> 2) * 64;
    int nchunks = (OC0 >> 7) + 1;

    const __nv_bfloat16* ob = g_outhb + (long)b * FEAT_ * HH * WW;

    float d[2][8][4];
#pragma unroll
    for (int mt = 0; mt < 2; mt++)
#pragma unroll
        for (int nt = 0; nt < 8; nt++)
#pragma unroll
            for (int i = 0; i < 4; i++) d[mt][nt][i] = 0.f;

    auto issue = [&](int c, int buf) {
        uint32_t ab = sm32 + buf * 34816;
        uint32_t bb = ab + 18432;
        int k0 = c * 64;
#pragma unroll
        for (int j = 0; j < 4; j++) {
            int i = tid + j * 256;
            int row = i >> 3, seg = i & 7;
            CP_ASYNC16(ab + row * 144 + seg * 16,
                       g_wsktb + (long)(OC0 + row) * FEAT_ + k0 + seg * 8);
        }
#pragma unroll
        for (int j = 0; j < 4; j++) {
            int i = tid + j * 256;
            int k = i >> 4, n8 = i & 15, yr = n8 >> 3, w8 = n8 & 7;
            uint32_t da = bb + k * 256 + yr * 128 + ((w8 * 16) ^ ((k & 7) << 4));
            const __nv_bfloat16* sa = ob + ((long)(k0 + k) * HH + y0 + yr) * WW + w8 * 8;
            CP_ASYNC16(da, sa);
        }
    };

    int kfl = lane & 15;
    int swz = (lane & 7) << 4;
    int col8b = (lane & 16) ? 1 : 0;

    issue(0, 0); CP_COMMIT();

    for (int c = 0; c < nchunks; c++) {
        if (c < nchunks - 1) { issue(c + 1, (c + 1) & 1); CP_COMMIT(); CP_WAIT1(); }
        else CP_WAIT0();
        __syncthreads();

        uint32_t ab = sm32 + (c & 1) * 34816;
        uint32_t bb = ab + 18432;
#pragma unroll
        for (int kk = 0; kk < 4; kk++) {
            uint32_t a[2][4];
#pragma unroll
            for (int mt = 0; mt < 2; mt++) {
                uint32_t aaddr = ab + 2 * ((m0 + mt * 16 + (lane & 15)) * 72
                                           + kk * 16 + ((lane >> 4) << 3));
                LDSM_X4(a[mt][0], a[mt][1], a[mt][2], a[mt][3], aaddr);
            }
            uint32_t rowbase = bb + (kk * 16 + kfl) * 256;
#pragma unroll
            for (int j = 0; j < 4; j++) {
                int seg = (n0 >> 3) + j * 2 + col8b;
                uint32_t baddr = rowbase + ((seg >> 3) * 128) + (uint32_t)(((seg & 7) * 16) ^ swz);
                uint32_t b0, b1, b2, b3;
                LDSM_X4T(b0, b1, b2, b3, baddr);
#pragma unroll
                for (int mt = 0; mt < 2; mt++) {
                    mma16(d[mt][j * 2],     a[mt][0], a[mt][1], a[mt][2], a[mt][3], b0, b1);
                    mma16(d[mt][j * 2 + 1], a[mt][0], a[mt][1], a[mt][2], a[mt][3], b2, b3);
                }
            }
        }
        __syncthreads();
    }

    int y = y0 + (n0 >> 6);
#pragma unroll
    for (int mt = 0; mt < 2; mt++) {
        int ocl = OC0 + m0 + mt * 16 + (lane >> 2);
        float bs0 = b_skip[ocl], bs1 = b_skip[ocl + 8];
#pragma unroll
        for (int nt = 0; nt < 8; nt++) {
            int w = nt * 8 + (lane & 3) * 2;
            long off = ((long)(b * CIN_ + ocl) * HH + y) * WW + w;
            float2 xv = *(const float2*)&x[off];
            *(float2*)&out[off] = make_float2(d[mt][nt][0] + xv.x + bs0,
                                              d[mt][nt][1] + xv.y + bs0);
            long off2 = off + (long)8 * HH * WW;
            float2 xv2 = *(const float2*)&x[off2];
            *(float2*)&out[off2] = make_float2(d[mt][nt][2] + xv2.x + bs1,
                                               d[mt][nt][3] + xv2.y + bs1);
        }
    }
}

// ---------------------------------------------------------------------------
extern "C" void kernel_launch(void* const* d_in, const int* in_sizes, int n_in,
                              void* d_out, int out_size) {
    const float* x      = (const float*)d_in[0];
    const float* w_i2s  = (const float*)d_in[1];
    const float* w_s2s  = (const float*)d_in[2];
    const float* w_skip = (const float*)d_in[3];
    const float* b_skip = (const float*)d_in[4];
    float* out = (float*)d_out;

    cudaFuncSetAttribute(i2s_bf16_kernel, cudaFuncAttributeMaxDynamicSharedMemorySize, I2S_SMEM);
    cudaFuncSetAttribute(lstm_scan_mma, cudaFuncAttributeMaxDynamicSharedMemorySize, SCAN_SMEM);
    cudaFuncSetAttribute(skip_bf16_kernel, cudaFuncAttributeMaxDynamicSharedMemorySize, SKIP_SMEM);

    // prep covers ALL merged index spaces: max is NB*CIN_*HH*4 = 1,572,864
    prep_kernel<<<(NB * CIN_ * HH * 4 + 255) / 256, 256>>>(x, w_i2s, w_s2s, w_skip);
    i2s_bf16_kernel<<<dim3(6, NB * 32), 256, I2S_SMEM>>>();
    lstm_scan_mma<<<dim3(24, 8), 256, SCAN_SMEM>>>();
    skip_bf16_kernel<<<dim3(3, NB * 32), 256, SKIP_SMEM>>>(x, b_skip, out);
}